// round 1
// baseline (speedup 1.0000x reference)
#include <cuda_runtime.h>
#include <cstdint>
#include <cstddef>

#define B_   32
#define T_   2048
#define D_   1024
#define U_   1024
#define MTOT (B_ * T_)   // 65536

#define BM 128
#define BN 128
#define BK 16
#define NCH (D_ / BK)    // 64 k-chunks

// Scratch (no cudaMalloc allowed): device globals
__device__ float g_qp[B_ * U_];            // q_proj + b1   [32,1024]
__device__ float g_part[8 * MTOT];         // score partials per N-slab [8][65536]
__device__ float g_ctxp[16 * B_ * D_];     // context partials per t-chunk [16][32][1024]

// ---------------------------------------------------------------------------
// helpers
// ---------------------------------------------------------------------------
__device__ __forceinline__ uint32_t f2tf32(float f) {
    uint32_t r;
    asm("cvt.rna.tf32.f32 %0, %1;" : "=r"(r) : "f"(f));
    return r;
}

__device__ __forceinline__ void mma_tf32(float d[4], const uint32_t a[4], const uint32_t b[2]) {
    asm volatile(
        "mma.sync.aligned.m16n8k8.row.col.f32.tf32.tf32.f32 "
        "{%0,%1,%2,%3}, {%4,%5,%6,%7}, {%8,%9}, {%0,%1,%2,%3};\n"
        : "+f"(d[0]), "+f"(d[1]), "+f"(d[2]), "+f"(d[3])
        : "r"(a[0]), "r"(a[1]), "r"(a[2]), "r"(a[3]),
          "r"(b[0]), "r"(b[1]));
}

// ---------------------------------------------------------------------------
// K1: q_proj[b,u] = b1[u] + sum_d query[b,d] * W1[d,u]   (fp32, cheap)
// grid (4, 32) x 256
// ---------------------------------------------------------------------------
__global__ void qproj_kernel(const float* __restrict__ query,
                             const float* __restrict__ W1,
                             const float* __restrict__ b1) {
    const int u = blockIdx.x * 256 + threadIdx.x;
    const int b = blockIdx.y;
    const float* q = query + b * D_;
    float acc = b1[u];
#pragma unroll 8
    for (int d = 0; d < D_; ++d)
        acc = fmaf(q[d], W1[(size_t)d * U_ + u], acc);
    g_qp[b * U_ + u] = acc;
}

// ---------------------------------------------------------------------------
// K2: the big fused kernel.
//   For each row r=(b,t):  vp[r, :] = values[r, :] @ W2   (tf32 mma, fp32 accum)
//   partial_score[slab, r] = sum_{u in slab} tanh(vp + qp[b,u] + b2[u]) * Wv[u]
// CTA tile 128x128, K chunk 16, double buffered smem, 8 warps (2x4),
// warp tile 64x32 -> 4x4 m16n8k8 mma tiles.
// grid (8 N-slabs, 512 M-tiles) x 256.  Deterministic (no atomics).
// ---------------------------------------------------------------------------
__global__ __launch_bounds__(256, 2)
void gemm_score_kernel(const float* __restrict__ values,
                       const float* __restrict__ W2,
                       const float* __restrict__ b2,
                       const float* __restrict__ Wv) {
    __shared__ __align__(16) uint32_t As[2][BM][BK + 4];   // stride 20 words (80B, 16B-aligned, conflict-free frag reads)
    __shared__ __align__(16) uint32_t Bs[2][BK][BN + 8];   // stride 136 words (544B, 16B-aligned, conflict-free frag reads)
    __shared__ float Red[BM][4];

    const int tid   = threadIdx.x;
    const int lane  = tid & 31;
    const int warp  = tid >> 5;
    const int warpM = warp >> 2;   // 0..1 -> 64 rows
    const int warpN = warp & 3;    // 0..3 -> 32 cols
    const int gid   = lane >> 2;   // 0..7
    const int tig   = lane & 3;    // 0..3
    const int bN      = blockIdx.x;           // 0..7
    const int rowBase = blockIdx.y * BM;      // 0..65408

    // global->smem mapping (2 float4 per thread per tile)
    const int ra0 = tid >> 2,           ca0 = (tid & 3) * 4;
    const int ra1 = (tid + 256) >> 2,   ca1 = (tid & 3) * 4;
    const int kb0 = tid >> 5,           cb0 = (tid & 31) * 4;
    const int kb1 = (tid + 256) >> 5,   cb1 = (tid & 31) * 4;

    float acc[4][4][4];
#pragma unroll
    for (int i = 0; i < 4; ++i)
#pragma unroll
        for (int j = 0; j < 4; ++j)
#pragma unroll
            for (int k = 0; k < 4; ++k) acc[i][j][k] = 0.f;

    float4 ga0, ga1, gb0, gb1;
    // prologue: load chunk 0
    ga0 = *(const float4*)(values + (size_t)(rowBase + ra0) * D_ + ca0);
    ga1 = *(const float4*)(values + (size_t)(rowBase + ra1) * D_ + ca1);
    gb0 = *(const float4*)(W2 + (size_t)kb0 * U_ + bN * BN + cb0);
    gb1 = *(const float4*)(W2 + (size_t)kb1 * U_ + bN * BN + cb1);
    {
        uint4 t;
        t.x = f2tf32(ga0.x); t.y = f2tf32(ga0.y); t.z = f2tf32(ga0.z); t.w = f2tf32(ga0.w);
        *(uint4*)&As[0][ra0][ca0] = t;
        t.x = f2tf32(ga1.x); t.y = f2tf32(ga1.y); t.z = f2tf32(ga1.z); t.w = f2tf32(ga1.w);
        *(uint4*)&As[0][ra1][ca1] = t;
        t.x = f2tf32(gb0.x); t.y = f2tf32(gb0.y); t.z = f2tf32(gb0.z); t.w = f2tf32(gb0.w);
        *(uint4*)&Bs[0][kb0][cb0] = t;
        t.x = f2tf32(gb1.x); t.y = f2tf32(gb1.y); t.z = f2tf32(gb1.z); t.w = f2tf32(gb1.w);
        *(uint4*)&Bs[0][kb1][cb1] = t;
    }
    __syncthreads();

    for (int kc = 0; kc < NCH; ++kc) {
        const int s = kc & 1;
        if (kc + 1 < NCH) {
            const int ko = (kc + 1) * BK;
            ga0 = *(const float4*)(values + (size_t)(rowBase + ra0) * D_ + ko + ca0);
            ga1 = *(const float4*)(values + (size_t)(rowBase + ra1) * D_ + ko + ca1);
            gb0 = *(const float4*)(W2 + (size_t)(ko + kb0) * U_ + bN * BN + cb0);
            gb1 = *(const float4*)(W2 + (size_t)(ko + kb1) * U_ + bN * BN + cb1);
        }
#pragma unroll
        for (int ks = 0; ks < 2; ++ks) {
            const int kk = ks * 8;
            uint32_t af[4][4];
#pragma unroll
            for (int mt = 0; mt < 4; ++mt) {
                const int m0 = warpM * 64 + mt * 16;
                af[mt][0] = As[s][m0 + gid][kk + tig];
                af[mt][1] = As[s][m0 + gid + 8][kk + tig];
                af[mt][2] = As[s][m0 + gid][kk + tig + 4];
                af[mt][3] = As[s][m0 + gid + 8][kk + tig + 4];
            }
            uint32_t bf[4][2];
#pragma unroll
            for (int nt = 0; nt < 4; ++nt) {
                const int n0 = warpN * 32 + nt * 8;
                bf[nt][0] = Bs[s][kk + tig][n0 + gid];
                bf[nt][1] = Bs[s][kk + tig + 4][n0 + gid];
            }
#pragma unroll
            for (int mt = 0; mt < 4; ++mt)
#pragma unroll
                for (int nt = 0; nt < 4; ++nt)
                    mma_tf32(acc[mt][nt], af[mt], bf[nt]);
        }
        if (kc + 1 < NCH) {
            const int s2 = s ^ 1;
            uint4 t;
            t.x = f2tf32(ga0.x); t.y = f2tf32(ga0.y); t.z = f2tf32(ga0.z); t.w = f2tf32(ga0.w);
            *(uint4*)&As[s2][ra0][ca0] = t;
            t.x = f2tf32(ga1.x); t.y = f2tf32(ga1.y); t.z = f2tf32(ga1.z); t.w = f2tf32(ga1.w);
            *(uint4*)&As[s2][ra1][ca1] = t;
            t.x = f2tf32(gb0.x); t.y = f2tf32(gb0.y); t.z = f2tf32(gb0.z); t.w = f2tf32(gb0.w);
            *(uint4*)&Bs[s2][kb0][cb0] = t;
            t.x = f2tf32(gb1.x); t.y = f2tf32(gb1.y); t.z = f2tf32(gb1.z); t.w = f2tf32(gb1.w);
            *(uint4*)&Bs[s2][kb1][cb1] = t;
        }
        __syncthreads();
    }

    // ---- fused epilogue: tanh + dot(Wv) -> per-row partial scores ----
    const int b = rowBase >> 11;   // rowBase / 2048 (M tiles never straddle a batch: 2048 % 128 == 0)
    float qv[4][2], wvv[4][2];
#pragma unroll
    for (int nt = 0; nt < 4; ++nt)
#pragma unroll
        for (int j = 0; j < 2; ++j) {
            const int n = bN * BN + warpN * 32 + nt * 8 + tig * 2 + j;
            qv[nt][j]  = g_qp[b * U_ + n] + b2[n];
            wvv[nt][j] = Wv[n];
        }
#pragma unroll
    for (int mt = 0; mt < 4; ++mt) {
        float s0 = 0.f, s1 = 0.f;
#pragma unroll
        for (int nt = 0; nt < 4; ++nt) {
            s0 += tanhf(acc[mt][nt][0] + qv[nt][0]) * wvv[nt][0];
            s0 += tanhf(acc[mt][nt][1] + qv[nt][1]) * wvv[nt][1];
            s1 += tanhf(acc[mt][nt][2] + qv[nt][0]) * wvv[nt][0];
            s1 += tanhf(acc[mt][nt][3] + qv[nt][1]) * wvv[nt][1];
        }
        s0 += __shfl_xor_sync(0xffffffffu, s0, 1);
        s0 += __shfl_xor_sync(0xffffffffu, s0, 2);
        s1 += __shfl_xor_sync(0xffffffffu, s1, 1);
        s1 += __shfl_xor_sync(0xffffffffu, s1, 2);
        if (tig == 0) {
            const int rl = warpM * 64 + mt * 16 + gid;
            Red[rl][warpN]     = s0;
            Red[rl + 8][warpN] = s1;
        }
    }
    __syncthreads();
    if (tid < BM) {
        const float s = Red[tid][0] + Red[tid][1] + Red[tid][2] + Red[tid][3];
        g_part[bN * MTOT + rowBase + tid] = s;
    }
}

// ---------------------------------------------------------------------------
// K3: per-batch softmax over T=2048 (sums the 8 N-slab partials first).
// bv is skipped: softmax is invariant to a constant shift. grid 32 x 256.
// ---------------------------------------------------------------------------
__global__ void softmax_kernel(float* __restrict__ out_w) {
    const int b = blockIdx.x;
    const int tid = threadIdx.x;
    __shared__ float red[256];
    const int base = b * T_;
    float sc[8];
#pragma unroll
    for (int i = 0; i < 8; ++i) {
        const int t = tid + i * 256;
        float s = 0.f;
#pragma unroll
        for (int p = 0; p < 8; ++p) s += g_part[p * MTOT + base + t];
        sc[i] = s;
    }
    float m = sc[0];
#pragma unroll
    for (int i = 1; i < 8; ++i) m = fmaxf(m, sc[i]);
    red[tid] = m;
    __syncthreads();
    for (int off = 128; off > 0; off >>= 1) {
        if (tid < off) red[tid] = fmaxf(red[tid], red[tid + off]);
        __syncthreads();
    }
    m = red[0];
    __syncthreads();
    float sum = 0.f;
#pragma unroll
    for (int i = 0; i < 8; ++i) {
        sc[i] = expf(sc[i] - m);
        sum += sc[i];
    }
    red[tid] = sum;
    __syncthreads();
    for (int off = 128; off > 0; off >>= 1) {
        if (tid < off) red[tid] += red[tid + off];
        __syncthreads();
    }
    const float inv = 1.f / red[0];
#pragma unroll
    for (int i = 0; i < 8; ++i)
        out_w[base + tid + i * 256] = sc[i] * inv;
}

// ---------------------------------------------------------------------------
// K4: partial context over a 128-wide t-chunk. grid (16, 32) x 256.
// Each thread owns 4 d's (float4). Deterministic (per-chunk partials).
// ---------------------------------------------------------------------------
__global__ void ctx_partial_kernel(const float* __restrict__ values,
                                   const float* __restrict__ w) {
    const int tc = blockIdx.x;   // 0..15
    const int b  = blockIdx.y;   // 0..31
    const int tid = threadIdx.x;
    __shared__ float ws[128];
    if (tid < 128) ws[tid] = w[b * T_ + tc * 128 + tid];
    __syncthreads();
    float4 acc = make_float4(0.f, 0.f, 0.f, 0.f);
    const float4* vp = (const float4*)(values + (size_t)(b * T_ + tc * 128) * D_) + tid;
#pragma unroll 4
    for (int tt = 0; tt < 128; ++tt) {
        const float wv = ws[tt];
        const float4 v = vp[(size_t)tt * 256];
        acc.x = fmaf(wv, v.x, acc.x);
        acc.y = fmaf(wv, v.y, acc.y);
        acc.z = fmaf(wv, v.z, acc.z);
        acc.w = fmaf(wv, v.w, acc.w);
    }
    *(float4*)&g_ctxp[(size_t)(tc * B_ + b) * D_ + tid * 4] = acc;
}

// ---------------------------------------------------------------------------
// K5: reduce the 16 t-chunk partials into the context output. grid 128 x 256.
// ---------------------------------------------------------------------------
__global__ void ctx_reduce_kernel(float* __restrict__ out_ctx) {
    const int i = blockIdx.x * 256 + threadIdx.x;   // < 32768
    float s = 0.f;
#pragma unroll
    for (int tc = 0; tc < 16; ++tc) s += g_ctxp[tc * (B_ * D_) + i];
    out_ctx[i] = s;
}

// ---------------------------------------------------------------------------
extern "C" void kernel_launch(void* const* d_in, const int* in_sizes, int n_in,
                              void* d_out, int out_size) {
    const float* query  = (const float*)d_in[0];
    const float* values = (const float*)d_in[1];
    const float* W1     = (const float*)d_in[2];
    const float* b1     = (const float*)d_in[3];
    const float* W2     = (const float*)d_in[4];
    const float* b2     = (const float*)d_in[5];
    const float* Wv     = (const float*)d_in[6];
    // d_in[7] = bv: softmax is shift-invariant, and bv only enters the score;
    // it cancels in the attention weights, so it is unused.
    (void)in_sizes; (void)n_in; (void)out_size;

    float* out_ctx = (float*)d_out;            // [32,1024]  = 32768 floats
    float* out_w   = (float*)d_out + B_ * D_;  // [32,2048,1] = 65536 floats

    qproj_kernel<<<dim3(4, 32), 256>>>(query, W1, b1);
    gemm_score_kernel<<<dim3(8, 512), 256>>>(values, W2, b2, Wv);
    softmax_kernel<<<32, 256>>>(out_w);
    ctx_partial_kernel<<<dim3(16, 32), 256>>>(values, out_w);
    ctx_reduce_kernel<<<128, 256>>>(out_ctx);
}

// round 2
// speedup vs baseline: 1.0013x; 1.0013x over previous
#include <cuda_runtime.h>
#include <cstdint>
#include <cstddef>

#define B_   32
#define T_   2048
#define D_   1024
#define U_   1024
#define MTOT (B_ * T_)   // 65536

#define BM 128
#define BN 128
#define BK 16
#define NCH (D_ / BK)    // 64 k-chunks

// Scratch (no cudaMalloc allowed): device globals
__device__ float g_qp[B_ * U_];            // q_proj + b1   [32,1024]
__device__ float g_part[8 * MTOT];         // score partials per N-slab [8][65536]
__device__ float g_ctxp[16 * B_ * D_];     // context partials per t-chunk [16][32][1024]

// ---------------------------------------------------------------------------
// helpers
// ---------------------------------------------------------------------------
__device__ __forceinline__ uint32_t f2tf32(float f) {
    uint32_t r;
    asm("cvt.rna.tf32.f32 %0, %1;" : "=r"(r) : "f"(f));
    return r;
}

__device__ __forceinline__ void mma_tf32(float d[4], const uint32_t a[4], const uint32_t b[2]) {
    asm volatile(
        "mma.sync.aligned.m16n8k8.row.col.f32.tf32.tf32.f32 "
        "{%0,%1,%2,%3}, {%4,%5,%6,%7}, {%8,%9}, {%0,%1,%2,%3};\n"
        : "+f"(d[0]), "+f"(d[1]), "+f"(d[2]), "+f"(d[3])
        : "r"(a[0]), "r"(a[1]), "r"(a[2]), "r"(a[3]),
          "r"(b[0]), "r"(b[1]));
}

// ---------------------------------------------------------------------------
// K1: q_proj[b,u] = b1[u] + sum_d query[b,d] * W1[d,u]   (fp32, cheap)
// grid (4, 32) x 256
// ---------------------------------------------------------------------------
__global__ void qproj_kernel(const float* __restrict__ query,
                             const float* __restrict__ W1,
                             const float* __restrict__ b1) {
    const int u = blockIdx.x * 256 + threadIdx.x;
    const int b = blockIdx.y;
    const float* q = query + b * D_;
    float acc = b1[u];
#pragma unroll 8
    for (int d = 0; d < D_; ++d)
        acc = fmaf(q[d], W1[(size_t)d * U_ + u], acc);
    g_qp[b * U_ + u] = acc;
}

// ---------------------------------------------------------------------------
// K2: the big fused kernel.
//   For each row r=(b,t):  vp[r, :] = values[r, :] @ W2   (tf32 mma, fp32 accum)
//   partial_score[slab, r] = sum_{u in slab} tanh(vp + qp[b,u] + b2[u]) * Wv[u]
// CTA tile 128x128, K chunk 16, double buffered smem, 8 warps (2x4),
// warp tile 64x32 -> 4x4 m16n8k8 mma tiles.
// grid (8 N-slabs, 512 M-tiles) x 256.  Deterministic (no atomics).
// ---------------------------------------------------------------------------
__global__ __launch_bounds__(256, 2)
void gemm_score_kernel(const float* __restrict__ values,
                       const float* __restrict__ W2,
                       const float* __restrict__ b2,
                       const float* __restrict__ Wv) {
    __shared__ __align__(16) uint32_t As[2][BM][BK + 4];   // stride 20 words (80B, 16B-aligned, conflict-free frag reads)
    __shared__ __align__(16) uint32_t Bs[2][BK][BN + 8];   // stride 136 words (544B, 16B-aligned, conflict-free frag reads)
    __shared__ float Red[BM][4];

    const int tid   = threadIdx.x;
    const int lane  = tid & 31;
    const int warp  = tid >> 5;
    const int warpM = warp >> 2;   // 0..1 -> 64 rows
    const int warpN = warp & 3;    // 0..3 -> 32 cols
    const int gid   = lane >> 2;   // 0..7
    const int tig   = lane & 3;    // 0..3
    const int bN      = blockIdx.x;           // 0..7
    const int rowBase = blockIdx.y * BM;      // 0..65408

    // global->smem mapping (2 float4 per thread per tile)
    const int ra0 = tid >> 2,           ca0 = (tid & 3) * 4;
    const int ra1 = (tid + 256) >> 2,   ca1 = (tid & 3) * 4;
    const int kb0 = tid >> 5,           cb0 = (tid & 31) * 4;
    const int kb1 = (tid + 256) >> 5,   cb1 = (tid & 31) * 4;

    float acc[4][4][4];
#pragma unroll
    for (int i = 0; i < 4; ++i)
#pragma unroll
        for (int j = 0; j < 4; ++j)
#pragma unroll
            for (int k = 0; k < 4; ++k) acc[i][j][k] = 0.f;

    float4 ga0, ga1, gb0, gb1;
    // prologue: load chunk 0
    ga0 = *(const float4*)(values + (size_t)(rowBase + ra0) * D_ + ca0);
    ga1 = *(const float4*)(values + (size_t)(rowBase + ra1) * D_ + ca1);
    gb0 = *(const float4*)(W2 + (size_t)kb0 * U_ + bN * BN + cb0);
    gb1 = *(const float4*)(W2 + (size_t)kb1 * U_ + bN * BN + cb1);
    {
        uint4 t;
        t.x = f2tf32(ga0.x); t.y = f2tf32(ga0.y); t.z = f2tf32(ga0.z); t.w = f2tf32(ga0.w);
        *(uint4*)&As[0][ra0][ca0] = t;
        t.x = f2tf32(ga1.x); t.y = f2tf32(ga1.y); t.z = f2tf32(ga1.z); t.w = f2tf32(ga1.w);
        *(uint4*)&As[0][ra1][ca1] = t;
        t.x = f2tf32(gb0.x); t.y = f2tf32(gb0.y); t.z = f2tf32(gb0.z); t.w = f2tf32(gb0.w);
        *(uint4*)&Bs[0][kb0][cb0] = t;
        t.x = f2tf32(gb1.x); t.y = f2tf32(gb1.y); t.z = f2tf32(gb1.z); t.w = f2tf32(gb1.w);
        *(uint4*)&Bs[0][kb1][cb1] = t;
    }
    __syncthreads();

    for (int kc = 0; kc < NCH; ++kc) {
        const int s = kc & 1;
        if (kc + 1 < NCH) {
            const int ko = (kc + 1) * BK;
            ga0 = *(const float4*)(values + (size_t)(rowBase + ra0) * D_ + ko + ca0);
            ga1 = *(const float4*)(values + (size_t)(rowBase + ra1) * D_ + ko + ca1);
            gb0 = *(const float4*)(W2 + (size_t)(ko + kb0) * U_ + bN * BN + cb0);
            gb1 = *(const float4*)(W2 + (size_t)(ko + kb1) * U_ + bN * BN + cb1);
        }
#pragma unroll
        for (int ks = 0; ks < 2; ++ks) {
            const int kk = ks * 8;
            uint32_t af[4][4];
#pragma unroll
            for (int mt = 0; mt < 4; ++mt) {
                const int m0 = warpM * 64 + mt * 16;
                af[mt][0] = As[s][m0 + gid][kk + tig];
                af[mt][1] = As[s][m0 + gid + 8][kk + tig];
                af[mt][2] = As[s][m0 + gid][kk + tig + 4];
                af[mt][3] = As[s][m0 + gid + 8][kk + tig + 4];
            }
            uint32_t bf[4][2];
#pragma unroll
            for (int nt = 0; nt < 4; ++nt) {
                const int n0 = warpN * 32 + nt * 8;
                bf[nt][0] = Bs[s][kk + tig][n0 + gid];
                bf[nt][1] = Bs[s][kk + tig + 4][n0 + gid];
            }
#pragma unroll
            for (int mt = 0; mt < 4; ++mt)
#pragma unroll
                for (int nt = 0; nt < 4; ++nt)
                    mma_tf32(acc[mt][nt], af[mt], bf[nt]);
        }
        if (kc + 1 < NCH) {
            const int s2 = s ^ 1;
            uint4 t;
            t.x = f2tf32(ga0.x); t.y = f2tf32(ga0.y); t.z = f2tf32(ga0.z); t.w = f2tf32(ga0.w);
            *(uint4*)&As[s2][ra0][ca0] = t;
            t.x = f2tf32(ga1.x); t.y = f2tf32(ga1.y); t.z = f2tf32(ga1.z); t.w = f2tf32(ga1.w);
            *(uint4*)&As[s2][ra1][ca1] = t;
            t.x = f2tf32(gb0.x); t.y = f2tf32(gb0.y); t.z = f2tf32(gb0.z); t.w = f2tf32(gb0.w);
            *(uint4*)&Bs[s2][kb0][cb0] = t;
            t.x = f2tf32(gb1.x); t.y = f2tf32(gb1.y); t.z = f2tf32(gb1.z); t.w = f2tf32(gb1.w);
            *(uint4*)&Bs[s2][kb1][cb1] = t;
        }
        __syncthreads();
    }

    // ---- fused epilogue: tanh + dot(Wv) -> per-row partial scores ----
    const int b = rowBase >> 11;   // rowBase / 2048 (M tiles never straddle a batch: 2048 % 128 == 0)
    float qv[4][2], wvv[4][2];
#pragma unroll
    for (int nt = 0; nt < 4; ++nt)
#pragma unroll
        for (int j = 0; j < 2; ++j) {
            const int n = bN * BN + warpN * 32 + nt * 8 + tig * 2 + j;
            qv[nt][j]  = g_qp[b * U_ + n] + b2[n];
            wvv[nt][j] = Wv[n];
        }
#pragma unroll
    for (int mt = 0; mt < 4; ++mt) {
        float s0 = 0.f, s1 = 0.f;
#pragma unroll
        for (int nt = 0; nt < 4; ++nt) {
            s0 += tanhf(acc[mt][nt][0] + qv[nt][0]) * wvv[nt][0];
            s0 += tanhf(acc[mt][nt][1] + qv[nt][1]) * wvv[nt][1];
            s1 += tanhf(acc[mt][nt][2] + qv[nt][0]) * wvv[nt][0];
            s1 += tanhf(acc[mt][nt][3] + qv[nt][1]) * wvv[nt][1];
        }
        s0 += __shfl_xor_sync(0xffffffffu, s0, 1);
        s0 += __shfl_xor_sync(0xffffffffu, s0, 2);
        s1 += __shfl_xor_sync(0xffffffffu, s1, 1);
        s1 += __shfl_xor_sync(0xffffffffu, s1, 2);
        if (tig == 0) {
            const int rl = warpM * 64 + mt * 16 + gid;
            Red[rl][warpN]     = s0;
            Red[rl + 8][warpN] = s1;
        }
    }
    __syncthreads();
    if (tid < BM) {
        const float s = Red[tid][0] + Red[tid][1] + Red[tid][2] + Red[tid][3];
        g_part[bN * MTOT + rowBase + tid] = s;
    }
}

// ---------------------------------------------------------------------------
// K3: per-batch softmax over T=2048 (sums the 8 N-slab partials first).
// bv is skipped: softmax is invariant to a constant shift. grid 32 x 256.
// ---------------------------------------------------------------------------
__global__ void softmax_kernel(float* __restrict__ out_w) {
    const int b = blockIdx.x;
    const int tid = threadIdx.x;
    __shared__ float red[256];
    const int base = b * T_;
    float sc[8];
#pragma unroll
    for (int i = 0; i < 8; ++i) {
        const int t = tid + i * 256;
        float s = 0.f;
#pragma unroll
        for (int p = 0; p < 8; ++p) s += g_part[p * MTOT + base + t];
        sc[i] = s;
    }
    float m = sc[0];
#pragma unroll
    for (int i = 1; i < 8; ++i) m = fmaxf(m, sc[i]);
    red[tid] = m;
    __syncthreads();
    for (int off = 128; off > 0; off >>= 1) {
        if (tid < off) red[tid] = fmaxf(red[tid], red[tid + off]);
        __syncthreads();
    }
    m = red[0];
    __syncthreads();
    float sum = 0.f;
#pragma unroll
    for (int i = 0; i < 8; ++i) {
        sc[i] = expf(sc[i] - m);
        sum += sc[i];
    }
    red[tid] = sum;
    __syncthreads();
    for (int off = 128; off > 0; off >>= 1) {
        if (tid < off) red[tid] += red[tid + off];
        __syncthreads();
    }
    const float inv = 1.f / red[0];
#pragma unroll
    for (int i = 0; i < 8; ++i)
        out_w[base + tid + i * 256] = sc[i] * inv;
}

// ---------------------------------------------------------------------------
// K4: partial context over a 128-wide t-chunk. grid (16, 32) x 256.
// Each thread owns 4 d's (float4). Deterministic (per-chunk partials).
// ---------------------------------------------------------------------------
__global__ void ctx_partial_kernel(const float* __restrict__ values,
                                   const float* __restrict__ w) {
    const int tc = blockIdx.x;   // 0..15
    const int b  = blockIdx.y;   // 0..31
    const int tid = threadIdx.x;
    __shared__ float ws[128];
    if (tid < 128) ws[tid] = w[b * T_ + tc * 128 + tid];
    __syncthreads();
    float4 acc = make_float4(0.f, 0.f, 0.f, 0.f);
    const float4* vp = (const float4*)(values + (size_t)(b * T_ + tc * 128) * D_) + tid;
#pragma unroll 4
    for (int tt = 0; tt < 128; ++tt) {
        const float wv = ws[tt];
        const float4 v = vp[(size_t)tt * 256];
        acc.x = fmaf(wv, v.x, acc.x);
        acc.y = fmaf(wv, v.y, acc.y);
        acc.z = fmaf(wv, v.z, acc.z);
        acc.w = fmaf(wv, v.w, acc.w);
    }
    *(float4*)&g_ctxp[(size_t)(tc * B_ + b) * D_ + tid * 4] = acc;
}

// ---------------------------------------------------------------------------
// K5: reduce the 16 t-chunk partials into the context output. grid 128 x 256.
// ---------------------------------------------------------------------------
__global__ void ctx_reduce_kernel(float* __restrict__ out_ctx) {
    const int i = blockIdx.x * 256 + threadIdx.x;   // < 32768
    float s = 0.f;
#pragma unroll
    for (int tc = 0; tc < 16; ++tc) s += g_ctxp[tc * (B_ * D_) + i];
    out_ctx[i] = s;
}

// ---------------------------------------------------------------------------
extern "C" void kernel_launch(void* const* d_in, const int* in_sizes, int n_in,
                              void* d_out, int out_size) {
    const float* query  = (const float*)d_in[0];
    const float* values = (const float*)d_in[1];
    const float* W1     = (const float*)d_in[2];
    const float* b1     = (const float*)d_in[3];
    const float* W2     = (const float*)d_in[4];
    const float* b2     = (const float*)d_in[5];
    const float* Wv     = (const float*)d_in[6];
    // d_in[7] = bv: softmax is shift-invariant, and bv only enters the score;
    // it cancels in the attention weights, so it is unused.
    (void)in_sizes; (void)n_in; (void)out_size;

    float* out_ctx = (float*)d_out;            // [32,1024]  = 32768 floats
    float* out_w   = (float*)d_out + B_ * D_;  // [32,2048,1] = 65536 floats

    qproj_kernel<<<dim3(4, 32), 256>>>(query, W1, b1);
    gemm_score_kernel<<<dim3(8, 512), 256>>>(values, W2, b2, Wv);
    softmax_kernel<<<32, 256>>>(out_w);
    ctx_partial_kernel<<<dim3(16, 32), 256>>>(values, out_w);
    ctx_reduce_kernel<<<128, 256>>>(out_ctx);
}

// round 4
// speedup vs baseline: 1.1058x; 1.1044x over previous
#include <cuda_runtime.h>
#include <cstdint>
#include <cstddef>

#define B_   32
#define T_   2048
#define D_   1024
#define U_   1024
#define MTOT (B_ * T_)   // 65536

#define BM 128
#define BN 128
#define BK 16
#define NCH (D_ / BK)    // 64 k-chunks
#define STAGES 4

// smem layout (floats)
#define A_STRIDE 20                                   // 16 + 4 pad (conflict-free frags)
#define B_STRIDE 136                                  // 128 + 8 pad
#define SM_B_OFF   (STAGES * BM * A_STRIDE)           // 10240
#define SM_RED_OFF (SM_B_OFF + STAGES * BK * B_STRIDE) // 18944
#define SMEM_FLOATS (SM_RED_OFF + BM * 4)             // 19456 -> 77824 bytes
#define SMEM_BYTES (SMEM_FLOATS * 4)

// Scratch (no cudaMalloc allowed): device globals
__device__ float g_qp[B_ * U_];            // q_proj + b1 + b2   [32,1024]
__device__ float g_part[8 * MTOT];         // score partials per N-slab [8][65536]
__device__ float g_ctxp[16 * B_ * D_];     // context partials per t-chunk [16][32][1024]

// ---------------------------------------------------------------------------
// helpers
// ---------------------------------------------------------------------------
__device__ __forceinline__ uint32_t smem_u32(const void* p) {
    uint32_t a;
    asm("{ .reg .u64 t; cvta.to.shared.u64 t, %1; cvt.u32.u64 %0, t; }" : "=r"(a) : "l"(p));
    return a;
}

__device__ __forceinline__ void cpa16(uint32_t dst, const void* src) {
    asm volatile("cp.async.cg.shared.global [%0], [%1], 16;" :: "r"(dst), "l"(src));
}

__device__ __forceinline__ void mma_tf32(float d[4], const uint32_t a[4], const uint32_t b[2]) {
    asm volatile(
        "mma.sync.aligned.m16n8k8.row.col.f32.tf32.tf32.f32 "
        "{%0,%1,%2,%3}, {%4,%5,%6,%7}, {%8,%9}, {%0,%1,%2,%3};\n"
        : "+f"(d[0]), "+f"(d[1]), "+f"(d[2]), "+f"(d[3])
        : "r"(a[0]), "r"(a[1]), "r"(a[2]), "r"(a[3]),
          "r"(b[0]), "r"(b[1]));
}

// ---------------------------------------------------------------------------
// dummy kernels so the GEMM is the 5th launch (ncu -s 5 capture target)
// ---------------------------------------------------------------------------
__global__ void noop_kernel() {}

// ---------------------------------------------------------------------------
// K1: q_proj[b,u] = b1[u] + b2[u] + sum_d query[b,d]*W1[d,u]. grid (4,32)x256
// ---------------------------------------------------------------------------
__global__ void qproj_kernel(const float* __restrict__ query,
                             const float* __restrict__ W1,
                             const float* __restrict__ b1,
                             const float* __restrict__ b2) {
    const int u = blockIdx.x * 256 + threadIdx.x;
    const int b = blockIdx.y;
    const float* q = query + b * D_;
    float a0 = b1[u] + b2[u], a1 = 0.f, a2 = 0.f, a3 = 0.f;
#pragma unroll 4
    for (int d = 0; d < 256; ++d) {
        a0 = fmaf(q[d],       W1[(size_t)d * U_ + u],         a0);
        a1 = fmaf(q[d + 256], W1[(size_t)(d + 256) * U_ + u], a1);
        a2 = fmaf(q[d + 512], W1[(size_t)(d + 512) * U_ + u], a2);
        a3 = fmaf(q[d + 768], W1[(size_t)(d + 768) * U_ + u], a3);
    }
    g_qp[b * U_ + u] = (a0 + a1) + (a2 + a3);
}

// ---------------------------------------------------------------------------
// K2: fused GEMM + tanh/Wv score. CTA tile 128x128, BK=16, 4-stage cp.async.
// 8 warps (2x4), warp tile 64x32 -> 4x4 m16n8k8 tf32 mma (HW truncation:
// operands are raw fp32; truncation error is zero-mean vs independent operand).
// grid (8 N-slabs, 512 M-tiles) x 256. Deterministic (no atomics).
// ---------------------------------------------------------------------------
__global__ __launch_bounds__(256, 2)
void gemm_score_kernel(const float* __restrict__ values,
                       const float* __restrict__ W2,
                       const float* __restrict__ b2,
                       const float* __restrict__ Wv) {
    extern __shared__ float sm[];
    float* Red = sm + SM_RED_OFF;
    const uint32_t sbA = smem_u32(sm);
    const uint32_t sbB = sbA + SM_B_OFF * 4;

    const int tid   = threadIdx.x;
    const int lane  = tid & 31;
    const int warp  = tid >> 5;
    const int warpM = warp >> 2;   // 0..1 -> 64 rows
    const int warpN = warp & 3;    // 0..3 -> 32 cols
    const int gid   = lane >> 2;   // 0..7
    const int tig   = lane & 3;    // 0..3
    const int bN      = blockIdx.x;           // 0..7
    const int rowBase = blockIdx.y * BM;

    // producer geometry (2 x 16B chunks each for A and B per stage)
    const int ra0 = tid >> 2,         ca0 = (tid & 3) * 4;
    const int ra1 = (tid + 256) >> 2, ca1 = (tid & 3) * 4;
    const int kb0 = tid >> 5,         cb0 = (tid & 31) * 4;
    const int kb1 = (tid + 256) >> 5, cb1 = (tid & 31) * 4;

    const float* gA0 = values + (size_t)(rowBase + ra0) * D_ + ca0;
    const float* gA1 = values + (size_t)(rowBase + ra1) * D_ + ca1;
    const float* gB0 = W2 + (size_t)kb0 * U_ + bN * BN + cb0;
    const float* gB1 = W2 + (size_t)kb1 * U_ + bN * BN + cb1;

    const uint32_t dA0 = sbA + (ra0 * A_STRIDE + ca0) * 4;
    const uint32_t dA1 = sbA + (ra1 * A_STRIDE + ca1) * 4;
    const uint32_t dB0 = sbB + (kb0 * B_STRIDE + cb0) * 4;
    const uint32_t dB1 = sbB + (kb1 * B_STRIDE + cb1) * 4;
    const uint32_t stA = BM * A_STRIDE * 4;   // stage stride bytes (A)
    const uint32_t stB = BK * B_STRIDE * 4;   // stage stride bytes (B)

    float acc[4][4][4];
#pragma unroll
    for (int i = 0; i < 4; ++i)
#pragma unroll
        for (int j = 0; j < 4; ++j)
#pragma unroll
            for (int k = 0; k < 4; ++k) acc[i][j][k] = 0.f;

    // prologue: stages 0..2
#pragma unroll
    for (int p = 0; p < STAGES - 1; ++p) {
        cpa16(dA0 + p * stA, gA0 + p * BK);
        cpa16(dA1 + p * stA, gA1 + p * BK);
        cpa16(dB0 + p * stB, gB0 + (size_t)p * BK * U_);
        cpa16(dB1 + p * stB, gB1 + (size_t)p * BK * U_);
        asm volatile("cp.async.commit_group;" ::: "memory");
    }

    const uint32_t* Au = (const uint32_t*)sm;
    const uint32_t* Bu = (const uint32_t*)(sm + SM_B_OFF);

    for (int kc = 0; kc < NCH; ++kc) {
        asm volatile("cp.async.wait_group %0;" :: "n"(STAGES - 2) : "memory");
        __syncthreads();

        // issue stage kc+3 into slot (kc+3)&3 (that slot was consumed at kc-1)
        if (kc + STAGES - 1 < NCH) {
            const int p = kc + STAGES - 1;
            const int s2 = p & (STAGES - 1);
            cpa16(dA0 + s2 * stA, gA0 + p * BK);
            cpa16(dA1 + s2 * stA, gA1 + p * BK);
            cpa16(dB0 + s2 * stB, gB0 + (size_t)p * BK * U_);
            cpa16(dB1 + s2 * stB, gB1 + (size_t)p * BK * U_);
        }
        asm volatile("cp.async.commit_group;" ::: "memory");

        // compute stage kc
        const int s = kc & (STAGES - 1);
        const uint32_t* As = Au + s * BM * A_STRIDE;
        const uint32_t* Bsr = Bu + s * BK * B_STRIDE;
#pragma unroll
        for (int ks = 0; ks < 2; ++ks) {
            const int kk = ks * 8;
            uint32_t af[4][4];
#pragma unroll
            for (int mt = 0; mt < 4; ++mt) {
                const int m0 = warpM * 64 + mt * 16;
                af[mt][0] = As[(m0 + gid) * A_STRIDE + kk + tig];
                af[mt][1] = As[(m0 + gid + 8) * A_STRIDE + kk + tig];
                af[mt][2] = As[(m0 + gid) * A_STRIDE + kk + tig + 4];
                af[mt][3] = As[(m0 + gid + 8) * A_STRIDE + kk + tig + 4];
            }
            uint32_t bf[4][2];
#pragma unroll
            for (int nt = 0; nt < 4; ++nt) {
                const int n0 = warpN * 32 + nt * 8;
                bf[nt][0] = Bsr[(kk + tig) * B_STRIDE + n0 + gid];
                bf[nt][1] = Bsr[(kk + tig + 4) * B_STRIDE + n0 + gid];
            }
#pragma unroll
            for (int mt = 0; mt < 4; ++mt)
#pragma unroll
                for (int nt = 0; nt < 4; ++nt)
                    mma_tf32(acc[mt][nt], af[mt], bf[nt]);
        }
    }

    // ---- fused epilogue: tanh + dot(Wv) -> per-row partial scores ----
    const int b = rowBase >> 11;   // 128 | 2048 so tiles never straddle a batch
    float qv[4][2], wvv[4][2];
#pragma unroll
    for (int nt = 0; nt < 4; ++nt)
#pragma unroll
        for (int j = 0; j < 2; ++j) {
            const int n = bN * BN + warpN * 32 + nt * 8 + tig * 2 + j;
            qv[nt][j]  = g_qp[b * U_ + n];
            wvv[nt][j] = Wv[n];
        }
#pragma unroll
    for (int mt = 0; mt < 4; ++mt) {
        float s0 = 0.f, s1 = 0.f;
#pragma unroll
        for (int nt = 0; nt < 4; ++nt) {
            s0 += tanhf(acc[mt][nt][0] + qv[nt][0]) * wvv[nt][0];
            s0 += tanhf(acc[mt][nt][1] + qv[nt][1]) * wvv[nt][1];
            s1 += tanhf(acc[mt][nt][2] + qv[nt][0]) * wvv[nt][0];
            s1 += tanhf(acc[mt][nt][3] + qv[nt][1]) * wvv[nt][1];
        }
        s0 += __shfl_xor_sync(0xffffffffu, s0, 1);
        s0 += __shfl_xor_sync(0xffffffffu, s0, 2);
        s1 += __shfl_xor_sync(0xffffffffu, s1, 1);
        s1 += __shfl_xor_sync(0xffffffffu, s1, 2);
        if (tig == 0) {
            const int rl = warpM * 64 + mt * 16 + gid;
            Red[rl * 4 + warpN]       = s0;
            Red[(rl + 8) * 4 + warpN] = s1;
        }
    }
    __syncthreads();
    if (tid < BM) {
        const float s = Red[tid * 4] + Red[tid * 4 + 1] + Red[tid * 4 + 2] + Red[tid * 4 + 3];
        g_part[bN * MTOT + rowBase + tid] = s;
    }
}

// ---------------------------------------------------------------------------
// K3: per-batch softmax over T=2048 (sums the 8 N-slab partials). grid 32x256.
// bv skipped (softmax shift-invariant).
// ---------------------------------------------------------------------------
__global__ void softmax_kernel(float* __restrict__ out_w) {
    const int b = blockIdx.x;
    const int tid = threadIdx.x;
    __shared__ float red[256];
    const int base = b * T_;
    float sc[8];
#pragma unroll
    for (int i = 0; i < 8; ++i) {
        const int t = tid + i * 256;
        float s = 0.f;
#pragma unroll
        for (int p = 0; p < 8; ++p) s += g_part[p * MTOT + base + t];
        sc[i] = s;
    }
    float m = sc[0];
#pragma unroll
    for (int i = 1; i < 8; ++i) m = fmaxf(m, sc[i]);
    red[tid] = m;
    __syncthreads();
    for (int off = 128; off > 0; off >>= 1) {
        if (tid < off) red[tid] = fmaxf(red[tid], red[tid + off]);
        __syncthreads();
    }
    m = red[0];
    __syncthreads();
    float sum = 0.f;
#pragma unroll
    for (int i = 0; i < 8; ++i) {
        sc[i] = expf(sc[i] - m);
        sum += sc[i];
    }
    red[tid] = sum;
    __syncthreads();
    for (int off = 128; off > 0; off >>= 1) {
        if (tid < off) red[tid] += red[tid + off];
        __syncthreads();
    }
    const float inv = 1.f / red[0];
#pragma unroll
    for (int i = 0; i < 8; ++i)
        out_w[base + tid + i * 256] = sc[i] * inv;
}

// ---------------------------------------------------------------------------
// K4: partial context over a 128-wide t-chunk. grid (16, 32) x 256.
// ---------------------------------------------------------------------------
__global__ void ctx_partial_kernel(const float* __restrict__ values,
                                   const float* __restrict__ w) {
    const int tc = blockIdx.x;
    const int b  = blockIdx.y;
    const int tid = threadIdx.x;
    __shared__ float ws[128];
    if (tid < 128) ws[tid] = w[b * T_ + tc * 128 + tid];
    __syncthreads();
    float4 acc = make_float4(0.f, 0.f, 0.f, 0.f);
    const float4* vp = (const float4*)(values + (size_t)(b * T_ + tc * 128) * D_) + tid;
#pragma unroll 4
    for (int tt = 0; tt < 128; ++tt) {
        const float wv = ws[tt];
        const float4 v = vp[(size_t)tt * 256];
        acc.x = fmaf(wv, v.x, acc.x);
        acc.y = fmaf(wv, v.y, acc.y);
        acc.z = fmaf(wv, v.z, acc.z);
        acc.w = fmaf(wv, v.w, acc.w);
    }
    *(float4*)&g_ctxp[(size_t)(tc * B_ + b) * D_ + tid * 4] = acc;
}

// ---------------------------------------------------------------------------
// K5: reduce the 16 t-chunk partials. grid 128 x 256.
// ---------------------------------------------------------------------------
__global__ void ctx_reduce_kernel(float* __restrict__ out_ctx) {
    const int i = blockIdx.x * 256 + threadIdx.x;
    float s = 0.f;
#pragma unroll
    for (int tc = 0; tc < 16; ++tc) s += g_ctxp[tc * (B_ * D_) + i];
    out_ctx[i] = s;
}

// ---------------------------------------------------------------------------
extern "C" void kernel_launch(void* const* d_in, const int* in_sizes, int n_in,
                              void* d_out, int out_size) {
    const float* query  = (const float*)d_in[0];
    const float* values = (const float*)d_in[1];
    const float* W1     = (const float*)d_in[2];
    const float* b1     = (const float*)d_in[3];
    const float* W2     = (const float*)d_in[4];
    const float* b2     = (const float*)d_in[5];
    const float* Wv     = (const float*)d_in[6];
    // d_in[7] = bv: cancels in softmax (shift-invariant), unused.
    (void)in_sizes; (void)n_in; (void)out_size;

    float* out_ctx = (float*)d_out;            // [32,1024]
    float* out_w   = (float*)d_out + B_ * D_;  // [32,2048,1]

    static int smem_set = 0;
    if (!smem_set) {
        cudaFuncSetAttribute(gemm_score_kernel,
                             cudaFuncAttributeMaxDynamicSharedMemorySize, SMEM_BYTES);
        smem_set = 1;
    }

    // 3 no-op launches so the GEMM is the 5th launch (ncu -s 5 capture)
    noop_kernel<<<1, 1>>>();
    noop_kernel<<<1, 1>>>();
    noop_kernel<<<1, 1>>>();
    qproj_kernel<<<dim3(4, 32), 256>>>(query, W1, b1, b2);
    gemm_score_kernel<<<dim3(8, 512), 256, SMEM_BYTES>>>(values, W2, b2, Wv);
    softmax_kernel<<<32, 256>>>(out_w);
    ctx_partial_kernel<<<dim3(16, 32), 256>>>(values, out_w);
    ctx_reduce_kernel<<<128, 256>>>(out_ctx);
}

// round 5
// speedup vs baseline: 1.8286x; 1.6537x over previous
#include <cuda_runtime.h>
#include <cuda_fp16.h>
#include <cstdint>
#include <cstddef>

#define B_   32
#define T_   2048
#define D_   1024
#define U_   1024
#define MTOT (B_ * T_)   // 65536

#define BM 128
#define BN 128
#define BK 32            // halfs per k-stage
#define NCH (D_ / BK)    // 32 k-chunks
#define STAGES 4

// smem (32-bit words): A[stage][128 rows][20], B[stage][128 rows][20]
#define AROW_W 20
#define STAGE_W (128 * AROW_W)                 // 2560 words per tile
#define SM_B_OFF_W (STAGES * STAGE_W)          // 10240
#define SM_RED_W   (2 * STAGES * STAGE_W)      // 20480
#define SMEM_WORDS (SM_RED_W + BM * 4)
#define SMEM_BYTES (SMEM_WORDS * 4)            // 84 KB

// Scratch (no cudaMalloc allowed): device globals
__device__ float g_qp[B_ * U_];                 // q_proj + b1 + b2
__device__ float g_qpp[8 * B_ * U_];            // qproj k-chunk partials
__device__ uint4 g_vh4[MTOT * D_ / 8];          // values fp16 [b,t,d]
__device__ uint4 g_w2h4[U_ * D_ / 8];           // W2^T fp16 [u][d]
__device__ float g_part[8 * MTOT];              // score partials per N-slab
__device__ float g_ctxp[16 * B_ * D_];          // context partials per t-chunk

// ---------------------------------------------------------------------------
__device__ __forceinline__ uint32_t smem_u32(const void* p) {
    uint32_t a;
    asm("{ .reg .u64 t; cvta.to.shared.u64 t, %1; cvt.u32.u64 %0, t; }" : "=r"(a) : "l"(p));
    return a;
}

__device__ __forceinline__ void cpa16(uint32_t dst, const void* src) {
    asm volatile("cp.async.cg.shared.global [%0], [%1], 16;" :: "r"(dst), "l"(src));
}

__device__ __forceinline__ void mma_f16(float d[4], const uint32_t a[4], const uint32_t b[2]) {
    asm volatile(
        "mma.sync.aligned.m16n8k16.row.col.f32.f16.f16.f32 "
        "{%0,%1,%2,%3}, {%4,%5,%6,%7}, {%8,%9}, {%0,%1,%2,%3};\n"
        : "+f"(d[0]), "+f"(d[1]), "+f"(d[2]), "+f"(d[3])
        : "r"(a[0]), "r"(a[1]), "r"(a[2]), "r"(a[3]),
          "r"(b[0]), "r"(b[1]));
}

// ---------------------------------------------------------------------------
// K1: qproj partials. grid (8 u-slabs, 8 k-chunks) x 128.
// Each thread owns one u, all 32 batches (32 FMAs per W1 load).
// ---------------------------------------------------------------------------
__global__ void qproj_part_kernel(const float* __restrict__ query,
                                  const float* __restrict__ W1) {
    __shared__ float qs[32 * 128];
    const int u  = blockIdx.x * 128 + threadIdx.x;
    const int d0 = blockIdx.y * 128;
    for (int i = threadIdx.x; i < 32 * 128; i += 128)
        qs[i] = query[(i >> 7) * D_ + d0 + (i & 127)];
    __syncthreads();
    float acc[32];
#pragma unroll
    for (int b = 0; b < 32; ++b) acc[b] = 0.f;
#pragma unroll 4
    for (int d = 0; d < 128; ++d) {
        const float w = W1[(size_t)(d0 + d) * U_ + u];
#pragma unroll
        for (int b = 0; b < 32; ++b) acc[b] = fmaf(qs[b * 128 + d], w, acc[b]);
    }
#pragma unroll
    for (int b = 0; b < 32; ++b)
        g_qpp[blockIdx.y * (B_ * U_) + b * U_ + u] = acc[b];
}

// K2: qproj reduce + biases. grid 128 x 256.
__global__ void qproj_red_kernel(const float* __restrict__ b1,
                                 const float* __restrict__ b2) {
    const int i = blockIdx.x * 256 + threadIdx.x;   // < 32768
    const int u = i & (U_ - 1);
    float s = b1[u] + b2[u];
#pragma unroll
    for (int k = 0; k < 8; ++k) s += g_qpp[k * (B_ * U_) + i];
    g_qp[i] = s;
}

// ---------------------------------------------------------------------------
// K3: values fp32 -> fp16. grid 32768 x 256, 8 elems/thread.
// ---------------------------------------------------------------------------
__global__ void cvt_vals_kernel(const float4* __restrict__ v) {
    const size_t i = (size_t)blockIdx.x * 256 + threadIdx.x;
    const float4 a = v[2 * i], b = v[2 * i + 1];
    const __half2 h0 = __floats2half2_rn(a.x, a.y);
    const __half2 h1 = __floats2half2_rn(a.z, a.w);
    const __half2 h2 = __floats2half2_rn(b.x, b.y);
    const __half2 h3 = __floats2half2_rn(b.z, b.w);
    uint4 o;
    o.x = *(const uint32_t*)&h0; o.y = *(const uint32_t*)&h1;
    o.z = *(const uint32_t*)&h2; o.w = *(const uint32_t*)&h3;
    g_vh4[i] = o;
}

// K4: W2 [d][u] -> W2^T fp16 [u][d]. grid (32,32) x (32,8).
__global__ void cvt_w2_kernel(const float* __restrict__ W2) {
    __shared__ float tile[32][33];
    const int u0 = blockIdx.x * 32, d0 = blockIdx.y * 32;
    const int tx = threadIdx.x, ty = threadIdx.y;
    __half* w2h = (__half*)g_w2h4;
#pragma unroll
    for (int i = 0; i < 32; i += 8)
        tile[ty + i][tx] = W2[(size_t)(d0 + ty + i) * U_ + u0 + tx];
    __syncthreads();
#pragma unroll
    for (int i = 0; i < 32; i += 8)
        w2h[(size_t)(u0 + ty + i) * D_ + d0 + tx] = __float2half_rn(tile[tx][ty + i]);
}

// ---------------------------------------------------------------------------
// K5 (5th launch -> ncu target): fused fp16 GEMM + tanh/Wv score.
// CTA 128x128, BK=32 halfs, 4-stage cp.async, 8 warps (2x4), warp 64x32,
// 4x4 m16n8k16 f16 mma with fp32 accum. grid (8, 512) x 256. Deterministic.
// ---------------------------------------------------------------------------
__global__ __launch_bounds__(256, 2)
void gemm_score_kernel(const float* __restrict__ Wv) {
    extern __shared__ float sm[];
    float* Red = sm + SM_RED_W;
    const uint32_t sbA = smem_u32(sm);
    const uint32_t sbB = sbA + SM_B_OFF_W * 4;

    const int tid   = threadIdx.x;
    const int lane  = tid & 31;
    const int warp  = tid >> 5;
    const int warpM = warp >> 2;
    const int warpN = warp & 3;
    const int gid   = lane >> 2;
    const int tig   = lane & 3;
    const int bN      = blockIdx.x;
    const int rowBase = blockIdx.y * BM;

    const __half* Vh  = (const __half*)g_vh4;
    const __half* W2h = (const __half*)g_w2h4;

    // producer: 2 A-chunks + 2 B-chunks (16B) per thread per stage
    const int rw0 = tid >> 1;                 // rows 0..127 (chunks 0..255)
    const int cw0 = (tid & 1) * 4;            // word offset 0|4
    const int rw1 = (tid + 256) >> 1;         // rows 128.. wait: chunks 256..511
    const int cw1 = ((tid + 256) & 1) * 4;
    // chunk c: row = c>>2, word = (c&3)*4  -> re-derive properly:
    const int cA0r = tid >> 2,         cA0w = (tid & 3) * 4;
    const int cA1r = (tid + 256) >> 2, cA1w = ((tid + 256) & 3) * 4;
    (void)rw0; (void)cw0; (void)rw1; (void)cw1;

    const __half* gA0 = Vh  + (size_t)(rowBase + cA0r) * D_ + cA0w * 2;
    const __half* gA1 = Vh  + (size_t)(rowBase + cA1r) * D_ + cA1w * 2;
    const __half* gB0 = W2h + (size_t)(bN * BN + cA0r) * D_ + cA0w * 2;
    const __half* gB1 = W2h + (size_t)(bN * BN + cA1r) * D_ + cA1w * 2;

    const uint32_t dA0 = sbA + (cA0r * AROW_W + cA0w) * 4;
    const uint32_t dA1 = sbA + (cA1r * AROW_W + cA1w) * 4;
    const uint32_t dB0 = sbB + (cA0r * AROW_W + cA0w) * 4;
    const uint32_t dB1 = sbB + (cA1r * AROW_W + cA1w) * 4;
    const uint32_t stg = STAGE_W * 4;   // stage stride bytes

    float acc[4][4][4];
#pragma unroll
    for (int i = 0; i < 4; ++i)
#pragma unroll
        for (int j = 0; j < 4; ++j)
#pragma unroll
            for (int k = 0; k < 4; ++k) acc[i][j][k] = 0.f;

#pragma unroll
    for (int p = 0; p < STAGES - 1; ++p) {
        cpa16(dA0 + p * stg, gA0 + p * BK);
        cpa16(dA1 + p * stg, gA1 + p * BK);
        cpa16(dB0 + p * stg, gB0 + p * BK);
        cpa16(dB1 + p * stg, gB1 + p * BK);
        asm volatile("cp.async.commit_group;" ::: "memory");
    }

    const uint32_t* Au = (const uint32_t*)sm;
    const uint32_t* Bu = Au + SM_B_OFF_W;

    for (int kc = 0; kc < NCH; ++kc) {
        asm volatile("cp.async.wait_group %0;" :: "n"(STAGES - 2) : "memory");
        __syncthreads();

        if (kc + STAGES - 1 < NCH) {
            const int p = kc + STAGES - 1;
            const int s2 = p & (STAGES - 1);
            cpa16(dA0 + s2 * stg, gA0 + p * BK);
            cpa16(dA1 + s2 * stg, gA1 + p * BK);
            cpa16(dB0 + s2 * stg, gB0 + p * BK);
            cpa16(dB1 + s2 * stg, gB1 + p * BK);
        }
        asm volatile("cp.async.commit_group;" ::: "memory");

        const int s = kc & (STAGES - 1);
        const uint32_t* As  = Au + s * STAGE_W;
        const uint32_t* Bsr = Bu + s * STAGE_W;
#pragma unroll
        for (int ks = 0; ks < 2; ++ks) {
            const int kw = ks * 8;  // word offset within row (k halfs 16*ks)
            uint32_t af[4][4];
#pragma unroll
            for (int mt = 0; mt < 4; ++mt) {
                const int m0 = warpM * 64 + mt * 16;
                af[mt][0] = As[(m0 + gid) * AROW_W + kw + tig];
                af[mt][1] = As[(m0 + gid + 8) * AROW_W + kw + tig];
                af[mt][2] = As[(m0 + gid) * AROW_W + kw + tig + 4];
                af[mt][3] = As[(m0 + gid + 8) * AROW_W + kw + tig + 4];
            }
            uint32_t bf[4][2];
#pragma unroll
            for (int nt = 0; nt < 4; ++nt) {
                const int n0 = warpN * 32 + nt * 8;
                bf[nt][0] = Bsr[(n0 + gid) * AROW_W + kw + tig];
                bf[nt][1] = Bsr[(n0 + gid) * AROW_W + kw + tig + 4];
            }
#pragma unroll
            for (int mt = 0; mt < 4; ++mt)
#pragma unroll
                for (int nt = 0; nt < 4; ++nt)
                    mma_f16(acc[mt][nt], af[mt], bf[nt]);
        }
    }

    // ---- fused epilogue ----
    const int b = rowBase >> 11;
    float qv[4][2], wvv[4][2];
#pragma unroll
    for (int nt = 0; nt < 4; ++nt)
#pragma unroll
        for (int j = 0; j < 2; ++j) {
            const int n = bN * BN + warpN * 32 + nt * 8 + tig * 2 + j;
            qv[nt][j]  = g_qp[b * U_ + n];
            wvv[nt][j] = Wv[n];
        }
#pragma unroll
    for (int mt = 0; mt < 4; ++mt) {
        float s0 = 0.f, s1 = 0.f;
#pragma unroll
        for (int nt = 0; nt < 4; ++nt) {
            s0 += tanhf(acc[mt][nt][0] + qv[nt][0]) * wvv[nt][0];
            s0 += tanhf(acc[mt][nt][1] + qv[nt][1]) * wvv[nt][1];
            s1 += tanhf(acc[mt][nt][2] + qv[nt][0]) * wvv[nt][0];
            s1 += tanhf(acc[mt][nt][3] + qv[nt][1]) * wvv[nt][1];
        }
        s0 += __shfl_xor_sync(0xffffffffu, s0, 1);
        s0 += __shfl_xor_sync(0xffffffffu, s0, 2);
        s1 += __shfl_xor_sync(0xffffffffu, s1, 1);
        s1 += __shfl_xor_sync(0xffffffffu, s1, 2);
        if (tig == 0) {
            const int rl = warpM * 64 + mt * 16 + gid;
            Red[rl * 4 + warpN]       = s0;
            Red[(rl + 8) * 4 + warpN] = s1;
        }
    }
    __syncthreads();
    if (tid < BM) {
        const float s = Red[tid * 4] + Red[tid * 4 + 1] + Red[tid * 4 + 2] + Red[tid * 4 + 3];
        g_part[bN * MTOT + rowBase + tid] = s;
    }
}

// ---------------------------------------------------------------------------
// K6: per-batch softmax over T=2048. grid 32 x 256. bv cancels.
// ---------------------------------------------------------------------------
__global__ void softmax_kernel(float* __restrict__ out_w) {
    const int b = blockIdx.x;
    const int tid = threadIdx.x;
    __shared__ float red[256];
    const int base = b * T_;
    float sc[8];
#pragma unroll
    for (int i = 0; i < 8; ++i) {
        const int t = tid + i * 256;
        float s = 0.f;
#pragma unroll
        for (int p = 0; p < 8; ++p) s += g_part[p * MTOT + base + t];
        sc[i] = s;
    }
    float m = sc[0];
#pragma unroll
    for (int i = 1; i < 8; ++i) m = fmaxf(m, sc[i]);
    red[tid] = m;
    __syncthreads();
    for (int off = 128; off > 0; off >>= 1) {
        if (tid < off) red[tid] = fmaxf(red[tid], red[tid + off]);
        __syncthreads();
    }
    m = red[0];
    __syncthreads();
    float sum = 0.f;
#pragma unroll
    for (int i = 0; i < 8; ++i) {
        sc[i] = expf(sc[i] - m);
        sum += sc[i];
    }
    red[tid] = sum;
    __syncthreads();
    for (int off = 128; off > 0; off >>= 1) {
        if (tid < off) red[tid] += red[tid + off];
        __syncthreads();
    }
    const float inv = 1.f / red[0];
#pragma unroll
    for (int i = 0; i < 8; ++i)
        out_w[base + tid + i * 256] = sc[i] * inv;
}

// ---------------------------------------------------------------------------
// K7: partial context from fp16 values. grid (16, 32) x 256, 4 halfs/thread.
// ---------------------------------------------------------------------------
__global__ void ctx_partial_kernel(const float* __restrict__ w) {
    const int tc = blockIdx.x;
    const int b  = blockIdx.y;
    const int tid = threadIdx.x;
    __shared__ float ws[128];
    if (tid < 128) ws[tid] = w[b * T_ + tc * 128 + tid];
    __syncthreads();
    float4 acc = make_float4(0.f, 0.f, 0.f, 0.f);
    const uint2* vp = (const uint2*)g_vh4
                    + ((size_t)(b * T_ + tc * 128) * D_) / 4 + tid;
#pragma unroll 4
    for (int tt = 0; tt < 128; ++tt) {
        const float wv = ws[tt];
        const uint2 v = vp[(size_t)tt * 256];
        const float2 f0 = __half22float2(*(const __half2*)&v.x);
        const float2 f1 = __half22float2(*(const __half2*)&v.y);
        acc.x = fmaf(wv, f0.x, acc.x);
        acc.y = fmaf(wv, f0.y, acc.y);
        acc.z = fmaf(wv, f1.x, acc.z);
        acc.w = fmaf(wv, f1.y, acc.w);
    }
    *(float4*)&g_ctxp[(size_t)(tc * B_ + b) * D_ + tid * 4] = acc;
}

// K8: reduce the 16 t-chunk partials. grid 128 x 256.
__global__ void ctx_reduce_kernel(float* __restrict__ out_ctx) {
    const int i = blockIdx.x * 256 + threadIdx.x;
    float s = 0.f;
#pragma unroll
    for (int tc = 0; tc < 16; ++tc) s += g_ctxp[tc * (B_ * D_) + i];
    out_ctx[i] = s;
}

// ---------------------------------------------------------------------------
extern "C" void kernel_launch(void* const* d_in, const int* in_sizes, int n_in,
                              void* d_out, int out_size) {
    const float* query  = (const float*)d_in[0];
    const float* values = (const float*)d_in[1];
    const float* W1     = (const float*)d_in[2];
    const float* b1     = (const float*)d_in[3];
    const float* W2     = (const float*)d_in[4];
    const float* b2     = (const float*)d_in[5];
    const float* Wv     = (const float*)d_in[6];
    // d_in[7] = bv: cancels in softmax (shift-invariant), unused.
    (void)in_sizes; (void)n_in; (void)out_size;

    float* out_ctx = (float*)d_out;            // [32,1024]
    float* out_w   = (float*)d_out + B_ * D_;  // [32,2048,1]

    static int smem_set = 0;
    if (!smem_set) {
        cudaFuncSetAttribute(gemm_score_kernel,
                             cudaFuncAttributeMaxDynamicSharedMemorySize, SMEM_BYTES);
        smem_set = 1;
    }

    qproj_part_kernel<<<dim3(8, 8), 128>>>(query, W1);       // 1
    qproj_red_kernel<<<128, 256>>>(b1, b2);                  // 2
    cvt_vals_kernel<<<MTOT * D_ / 8 / 256, 256>>>((const float4*)values); // 3
    cvt_w2_kernel<<<dim3(32, 32), dim3(32, 8)>>>(W2);        // 4
    gemm_score_kernel<<<dim3(8, 512), 256, SMEM_BYTES>>>(Wv);// 5 (ncu)
    softmax_kernel<<<32, 256>>>(out_w);                      // 6
    ctx_partial_kernel<<<dim3(16, 32), 256>>>(out_w);        // 7
    ctx_reduce_kernel<<<128, 256>>>(out_ctx);                // 8
}